// round 2
// baseline (speedup 1.0000x reference)
#include <cuda_runtime.h>

#define BATCH 4
#define NPB   8192
#define MS    2048
#define KNB   64
#define FDIM  64
#define NPTS  (BATCH*NPB)
#define CAP   1024

__device__ float g_xw1[NPTS * 64];   // x @ W1[:64,:]
__device__ int   g_samp[BATCH * MS]; // FPS indices (local per cloud)

// ---------------- Kernel A: X' = x @ W1[0:64,:] ----------------
__global__ void __launch_bounds__(256) xw1_kernel(const float* __restrict__ x,
                                                  const float* __restrict__ W1) {
    __shared__ float W1s[64 * 64];
    __shared__ float xs[256];
    int tid = threadIdx.x;
    for (int i = tid; i < 64 * 64; i += 256) W1s[i] = W1[i];
    xs[tid] = x[(size_t)blockIdx.x * 256 + tid];   // 4 rows x 64
    __syncthreads();
    int rl = tid >> 6;          // local row 0..3
    int c  = tid & 63;
    float acc = 0.f;
    #pragma unroll
    for (int k = 0; k < 64; k++) acc = fmaf(xs[rl * 64 + k], W1s[k * 64 + c], acc);
    g_xw1[(size_t)blockIdx.x * 256 + rl * 64 + c] = acc;
}

// ---------------- Kernel B: farthest point sampling ----------------
// One 1024-thread block per cloud; 8 points per thread in registers.
// Arithmetic replicates XLA fp32 exactly: rn sub, rn mul, ((xx+yy)+zz), min, argmax first-index.
__global__ void __launch_bounds__(1024, 1) fps_kernel(const float* __restrict__ pos) {
    int b = blockIdx.x;
    int tid = threadIdx.x;
    const float* pb = pos + (size_t)b * NPB * 3;

    float px[8], py[8], pz[8], md[8];
    #pragma unroll
    for (int i = 0; i < 8; i++) {
        int p = i * 1024 + tid;
        px[i] = pb[3 * p];
        py[i] = pb[3 * p + 1];
        pz[i] = pb[3 * p + 2];
        md[i] = __int_as_float(0x7f800000);  // +inf
    }
    float sx = pb[0], sy = pb[1], sz = pb[2];
    if (tid == 0) g_samp[b * MS] = 0;

    __shared__ float swv[32];
    __shared__ int   swi[32];
    int wid = tid >> 5, lane = tid & 31;

    for (int t = 1; t < MS; t++) {
        float bv = -1.0f;
        int   bi = 0x7fffffff;
        #pragma unroll
        for (int i = 0; i < 8; i++) {
            float dx = px[i] - sx;
            float dy = py[i] - sy;
            float dz = pz[i] - sz;
            float xx = __fmul_rn(dx, dx);
            float yy = __fmul_rn(dy, dy);
            float zz = __fmul_rn(dz, dz);
            float d2 = __fadd_rn(__fadd_rn(xx, yy), zz);
            float m  = fminf(md[i], d2);
            md[i] = m;
            if (m > bv) { bv = m; bi = i * 1024 + tid; }  // idx ascending -> first-index ties
        }
        // warp argmax (value desc, index asc on ties)
        #pragma unroll
        for (int off = 16; off; off >>= 1) {
            float ov = __shfl_down_sync(0xffffffffu, bv, off);
            int   oi = __shfl_down_sync(0xffffffffu, bi, off);
            if (ov > bv || (ov == bv && oi < bi)) { bv = ov; bi = oi; }
        }
        if (lane == 0) { swv[wid] = bv; swi[wid] = bi; }
        __syncthreads();
        bv = swv[lane]; bi = swi[lane];
        #pragma unroll
        for (int off = 16; off; off >>= 1) {
            float ov = __shfl_down_sync(0xffffffffu, bv, off);
            int   oi = __shfl_down_sync(0xffffffffu, bi, off);
            if (ov > bv || (ov == bv && oi < bi)) { bv = ov; bi = oi; }
        }
        bi = __shfl_sync(0xffffffffu, bi, 0);
        sx = __ldg(&pb[3 * bi]);
        sy = __ldg(&pb[3 * bi + 1]);
        sz = __ldg(&pb[3 * bi + 2]);
        if (tid == 0) g_samp[b * MS + t] = bi;
        __syncthreads();  // protect swv/swi reuse
    }
}

// ---------------- Kernel C: per-sample ball query + MLP + maxpool ----------------
// smem layout offsets (bytes)
#define SM_CAND   0
#define SM_H1T    (CAP * 8)                    // 8192
#define SM_H2T    (SM_H1T + 64 * 68 * 4)       // +17408
#define SM_W2     (SM_H2T + 64 * 68 * 4)       // +17408
#define SM_W3     (SM_W2 + 64 * 64 * 4)        // +16384
#define SM_W1P    (SM_W3 + 64 * 128 * 4)       // +32768
#define SM_B1     (SM_W1P + 192 * 4)
#define SM_B2     (SM_B1 + 64 * 4)
#define SM_B3     (SM_B2 + 64 * 4)
#define SM_MAX    (SM_B3 + 128 * 4)
#define SM_CNT    (SM_MAX + 128 * 4)
#define SMEM2     (SM_CNT + 64)

extern __shared__ char smem_raw[];

__global__ void __launch_bounds__(256, 2) sa_kernel(
    const float* __restrict__ pos,
    const float* __restrict__ W1, const float* __restrict__ b1,
    const float* __restrict__ W2, const float* __restrict__ b2,
    const float* __restrict__ W3, const float* __restrict__ b3,
    float* __restrict__ out, int out_size) {

    unsigned long long* cand = (unsigned long long*)(smem_raw + SM_CAND);
    float* h1T  = (float*)(smem_raw + SM_H1T);
    float* h2T  = (float*)(smem_raw + SM_H2T);
    float* W2s  = (float*)(smem_raw + SM_W2);
    float* W3s  = (float*)(smem_raw + SM_W3);
    float* W1ps = (float*)(smem_raw + SM_W1P);
    float* b1s  = (float*)(smem_raw + SM_B1);
    float* b2s  = (float*)(smem_raw + SM_B2);
    float* b3s  = (float*)(smem_raw + SM_B3);
    int*   smaxI = (int*)(smem_raw + SM_MAX);
    int*   scnt  = (int*)(smem_raw + SM_CNT);

    const int tid = threadIdx.x;
    const int row = blockIdx.x;              // global output row = b*MS + m
    const int b   = row >> 11;               // /MS
    const int g0  = b * NPB;

    // load weights / init
    for (int i = tid; i < 4096; i += 256) W2s[i] = W2[i];
    for (int i = tid; i < 8192; i += 256) W3s[i] = W3[i];
    if (tid < 192) W1ps[tid] = W1[64 * 64 + tid];
    if (tid < 64)  { b1s[tid] = b1[tid]; b2s[tid] = b2[tid]; }
    if (tid < 128) { b3s[tid] = b3[tid]; smaxI[tid] = 0; }
    if (tid == 0)  *scnt = 0;
    for (int i = tid; i < CAP; i += 256) cand[i] = 0xffffffffffffffffull;
    __syncthreads();

    const float* pb = pos + (size_t)g0 * 3;
    int sl = g_samp[row];
    float cx = pb[3 * sl], cy = pb[3 * sl + 1], cz = pb[3 * sl + 2];
    const float R2 = (float)(0.2 * 0.2);

    // radius scan (exact fp32 semantics to match reference boundary)
    for (int p = tid; p < NPB; p += 256) {
        float dx = pb[3 * p] - cx;
        float dy = pb[3 * p + 1] - cy;
        float dz = pb[3 * p + 2] - cz;
        float d2 = __fadd_rn(__fadd_rn(__fmul_rn(dx, dx), __fmul_rn(dy, dy)), __fmul_rn(dz, dz));
        if (d2 <= R2) {
            int s = atomicAdd(scnt, 1);
            if (s < CAP)
                cand[s] = ((unsigned long long)__float_as_uint(d2) << 32) | (unsigned)p;
        }
    }
    __syncthreads();
    int n = *scnt; if (n > CAP) n = CAP;

    // bitonic sort ascending (u64 keys: d2 bits major, index minor -> stable like lax.top_k)
    for (int k = 2; k <= CAP; k <<= 1) {
        for (int j = k >> 1; j > 0; j >>= 1) {
            __syncthreads();
            for (int i = tid; i < CAP; i += 256) {
                int ixj = i ^ j;
                if (ixj > i) {
                    unsigned long long a = cand[i], c2 = cand[ixj];
                    bool asc = ((i & k) == 0);
                    if ((a > c2) == asc) { cand[i] = c2; cand[ixj] = a; }
                }
            }
        }
    }
    __syncthreads();
    int nv = n < KNB ? n : KNB;

    // h1 = relu(X'[j] + relpos @ W1p + b1), stored transposed [c][n] with stride 68
    for (int p = tid; p < 64 * 64; p += 256) {
        int nn = p >> 6, c = p & 63;
        float v = 0.f;
        if (nn < nv) {
            int j = (int)(unsigned)(cand[nn] & 0xffffffffull);
            float rx = pb[3 * j] - cx;
            float ry = pb[3 * j + 1] - cy;
            float rz = pb[3 * j + 2] - cz;
            v = g_xw1[(size_t)(g0 + j) * 64 + c];
            v = fmaf(rx, W1ps[c], v);
            v = fmaf(ry, W1ps[64 + c], v);
            v = fmaf(rz, W1ps[128 + c], v);
            v = fmaxf(v + b1s[c], 0.f);
        }
        h1T[c * 68 + nn] = v;
    }
    __syncthreads();

    // layer 2: h2 = relu(h1 @ W2 + b2); 4x4 register tiles
    {
        int tn = tid >> 4, tc = tid & 15;
        float acc[4][4];
        #pragma unroll
        for (int i = 0; i < 4; i++)
            #pragma unroll
            for (int j = 0; j < 4; j++) acc[i][j] = b2s[tc * 4 + j];
        #pragma unroll 8
        for (int k = 0; k < 64; k++) {
            float4 a = *(const float4*)(h1T + k * 68 + tn * 4);
            float4 w = *(const float4*)(W2s + k * 64 + tc * 4);
            const float av[4] = {a.x, a.y, a.z, a.w};
            const float wv[4] = {w.x, w.y, w.z, w.w};
            #pragma unroll
            for (int i = 0; i < 4; i++)
                #pragma unroll
                for (int j = 0; j < 4; j++) acc[i][j] = fmaf(av[i], wv[j], acc[i][j]);
        }
        #pragma unroll
        for (int i = 0; i < 4; i++)
            #pragma unroll
            for (int j = 0; j < 4; j++)
                h2T[(tc * 4 + j) * 68 + tn * 4 + i] = fmaxf(acc[i][j], 0.f);
    }
    __syncthreads();

    // layer 3: h3 = relu(h2 @ W3 + b3), fused maxpool over valid rows
    {
        int tn = tid >> 4, tc = tid & 15;
        float acc[4][8];
        #pragma unroll
        for (int i = 0; i < 4; i++)
            #pragma unroll
            for (int j = 0; j < 8; j++) acc[i][j] = b3s[tc * 8 + j];
        #pragma unroll 4
        for (int k = 0; k < 64; k++) {
            float4 a  = *(const float4*)(h2T + k * 68 + tn * 4);
            float4 w0 = *(const float4*)(W3s + k * 128 + tc * 8);
            float4 w1 = *(const float4*)(W3s + k * 128 + tc * 8 + 4);
            const float av[4] = {a.x, a.y, a.z, a.w};
            const float wv[8] = {w0.x, w0.y, w0.z, w0.w, w1.x, w1.y, w1.z, w1.w};
            #pragma unroll
            for (int i = 0; i < 4; i++)
                #pragma unroll
                for (int j = 0; j < 8; j++) acc[i][j] = fmaf(av[i], wv[j], acc[i][j]);
        }
        if (tn * 4 < nv) {  // at least one valid row in this tile
            int vrows = nv - tn * 4; if (vrows > 4) vrows = 4;
            #pragma unroll
            for (int j = 0; j < 8; j++) {
                float m = 0.f;
                for (int i = 0; i < vrows; i++) m = fmaxf(m, fmaxf(acc[i][j], 0.f));
                atomicMax(&smaxI[tc * 8 + j], __float_as_int(m));  // nonneg floats: int order == float order
            }
        }
    }
    __syncthreads();

    // outputs: [B*M,128] feat, then [B*M,3] pos, then [B*M] batch (as float)
    const int OUT1 = BATCH * MS * 128;
    const int OUT2 = OUT1 + BATCH * MS * 3;
    const int OUT3 = OUT2 + BATCH * MS;
    if (tid < 128) out[(size_t)row * 128 + tid] = __int_as_float(smaxI[tid]);
    if (out_size >= OUT2 && tid == 128) {
        float* po = out + OUT1 + (size_t)row * 3;
        po[0] = cx; po[1] = cy; po[2] = cz;
    }
    if (out_size >= OUT3 && tid == 129) out[OUT2 + row] = (float)b;
}

extern "C" void kernel_launch(void* const* d_in, const int* in_sizes, int n_in,
                              void* d_out, int out_size) {
    const float* x   = (const float*)d_in[0];
    const float* pos = (const float*)d_in[1];
    // d_in[2] = batch (implicit by layout)
    const float* W1 = (const float*)d_in[3];
    const float* b1 = (const float*)d_in[4];
    const float* W2 = (const float*)d_in[5];
    const float* b2 = (const float*)d_in[6];
    const float* W3 = (const float*)d_in[7];
    const float* b3 = (const float*)d_in[8];

    cudaFuncSetAttribute(sa_kernel, cudaFuncAttributeMaxDynamicSharedMemorySize, SMEM2);

    xw1_kernel<<<NPTS / 4, 256>>>(x, W1);
    fps_kernel<<<BATCH, 1024>>>(pos);
    sa_kernel<<<BATCH * MS, 256, SMEM2>>>(pos, W1, b1, W2, b2, W3, b3,
                                          (float*)d_out, out_size);
}

// round 3
// speedup vs baseline: 1.7209x; 1.7209x over previous
#include <cuda_runtime.h>

#define BATCH 4
#define NPB   8192
#define MS    2048
#define KNB   64
#define FDIM  64
#define NPTS  (BATCH*NPB)
#define CAP   1024

__device__ float g_xw1[NPTS * 64];   // x @ W1[:64,:]
__device__ int   g_samp[BATCH * MS]; // FPS indices (local per cloud)
__device__ float g_px[NPTS], g_py[NPTS], g_pz[NPTS];  // SoA positions

// ---------- packed f32x2 helpers (bit-exact per-lane rn) ----------
__device__ __forceinline__ unsigned long long pk2(float a, float b) {
    unsigned long long r;
    asm("mov.b64 %0,{%1,%2};" : "=l"(r) : "f"(a), "f"(b));
    return r;
}
__device__ __forceinline__ void upk2(unsigned long long v, float& a, float& b) {
    asm("mov.b64 {%0,%1},%2;" : "=f"(a), "=f"(b) : "l"(v));
}
__device__ __forceinline__ unsigned long long fma2(unsigned long long a, unsigned long long b, unsigned long long c) {
    unsigned long long d;
    asm("fma.rn.f32x2 %0,%1,%2,%3;" : "=l"(d) : "l"(a), "l"(b), "l"(c));
    return d;
}
__device__ __forceinline__ unsigned long long mul2(unsigned long long a, unsigned long long b) {
    unsigned long long d;
    asm("mul.rn.f32x2 %0,%1,%2;" : "=l"(d) : "l"(a), "l"(b));
    return d;
}
__device__ __forceinline__ unsigned long long add2(unsigned long long a, unsigned long long b) {
    unsigned long long d;
    asm("add.rn.f32x2 %0,%1,%2;" : "=l"(d) : "l"(a), "l"(b));
    return d;
}

// ---------------- Kernel S: AoS -> SoA transpose of pos ----------------
__global__ void __launch_bounds__(256) soa_kernel(const float* __restrict__ pos) {
    __shared__ float s[768];
    int tid = threadIdx.x;
    size_t base = (size_t)blockIdx.x * 768;
    s[tid]       = pos[base + tid];
    s[256 + tid] = pos[base + 256 + tid];
    s[512 + tid] = pos[base + 512 + tid];
    __syncthreads();
    int p = blockIdx.x * 256 + tid;
    g_px[p] = s[tid * 3];
    g_py[p] = s[tid * 3 + 1];
    g_pz[p] = s[tid * 3 + 2];
}

// ---------------- Kernel A: X' = x @ W1[0:64,:] ----------------
__global__ void __launch_bounds__(256) xw1_kernel(const float* __restrict__ x,
                                                  const float* __restrict__ W1) {
    __shared__ float W1s[64 * 64];
    __shared__ float xs[256];
    int tid = threadIdx.x;
    for (int i = tid; i < 64 * 64; i += 256) W1s[i] = W1[i];
    xs[tid] = x[(size_t)blockIdx.x * 256 + tid];   // 4 rows x 64
    __syncthreads();
    int rl = tid >> 6;          // local row 0..3
    int c  = tid & 63;
    float acc = 0.f;
    #pragma unroll
    for (int k = 0; k < 64; k++) acc = fmaf(xs[rl * 64 + k], W1s[k * 64 + c], acc);
    g_xw1[(size_t)blockIdx.x * 256 + rl * 64 + c] = acc;
}

// ---------------- Kernel B: farthest point sampling (packed f32x2) ----------------
// One 512-thread block per cloud; 16 points per thread (8 packed pairs) in registers.
// Exact XLA fp32 semantics: rn sub (via fma a*1-b), rn muls, ((xx+yy)+zz), fminf,
// argmax first-index tie-break (value desc, index asc).
__global__ void __launch_bounds__(512, 1) fps_kernel() {
    const int b = blockIdx.x;
    const int tid = threadIdx.x;
    const int lane = tid & 31, wid = tid >> 5;
    const float* px = g_px + b * NPB;
    const float* py = g_py + b * NPB;
    const float* pz = g_pz + b * NPB;

    const unsigned long long ONE2 = pk2(1.0f, 1.0f);

    unsigned long long X2[8], Y2[8], Z2[8];
    float md[16];
    #pragma unroll
    for (int g = 0; g < 8; g++) {
        int p0 = (2 * g) * 512 + tid;
        int p1 = (2 * g + 1) * 512 + tid;
        X2[g] = pk2(px[p0], px[p1]);
        Y2[g] = pk2(py[p0], py[p1]);
        Z2[g] = pk2(pz[p0], pz[p1]);
        md[2 * g] = __int_as_float(0x7f800000);
        md[2 * g + 1] = __int_as_float(0x7f800000);
    }
    float sx = px[0], sy = py[0], sz = pz[0];
    if (tid == 0) g_samp[b * MS] = 0;

    __shared__ unsigned swv[16];
    __shared__ int swi[16];
    __shared__ float sbx[3];

    for (int t = 1; t < MS; t++) {
        unsigned long long nsx2 = pk2(-sx, -sx);
        unsigned long long nsy2 = pk2(-sy, -sy);
        unsigned long long nsz2 = pk2(-sz, -sz);

        float bv = -1.0f;
        int   bi = 0x7fffffff;
        #pragma unroll
        for (int g = 0; g < 8; g++) {
            unsigned long long dx2 = fma2(X2[g], ONE2, nsx2);  // exact px - sx
            unsigned long long dy2 = fma2(Y2[g], ONE2, nsy2);
            unsigned long long dz2 = fma2(Z2[g], ONE2, nsz2);
            unsigned long long xx2 = mul2(dx2, dx2);
            unsigned long long yy2 = mul2(dy2, dy2);
            unsigned long long zz2 = mul2(dz2, dz2);
            unsigned long long d22 = add2(add2(xx2, yy2), zz2);
            float d0, d1;
            upk2(d22, d0, d1);
            float m0 = fminf(md[2 * g], d0);     md[2 * g] = m0;
            float m1 = fminf(md[2 * g + 1], d1); md[2 * g + 1] = m1;
            if (m0 > bv) { bv = m0; bi = (2 * g) * 512 + tid; }      // ascending idx order
            if (m1 > bv) { bv = m1; bi = (2 * g + 1) * 512 + tid; }
        }
        // stage 1: warp argmax via redux (value desc, first index on ties)
        unsigned vb = __float_as_uint(bv);              // md >= 0 -> bits monotone
        unsigned V = __reduce_max_sync(0xffffffffu, vb);
        unsigned I = __reduce_min_sync(0xffffffffu, (vb == V) ? (unsigned)bi : 0x7fffffffu);
        if (lane == 0) { swv[wid] = V; swi[wid] = (int)I; }
        __syncthreads();
        // stage 2: warp 0 reduces the 16 warp winners
        if (wid == 0) {
            unsigned v  = (lane < 16) ? swv[lane] : 0u;
            unsigned ii = (lane < 16) ? (unsigned)swi[lane] : 0x7fffffffu;
            unsigned Vg = __reduce_max_sync(0xffffffffu, v);
            unsigned Ig = __reduce_min_sync(0xffffffffu, (v == Vg) ? ii : 0x7fffffffu);
            if (lane == 0) {
                g_samp[b * MS + t] = (int)Ig;
                sbx[0] = px[Ig]; sbx[1] = py[Ig]; sbx[2] = pz[Ig];
            }
        }
        __syncthreads();
        sx = sbx[0]; sy = sbx[1]; sz = sbx[2];
    }
}

// ---------------- Kernel C: per-sample ball query + MLP + maxpool ----------------
// smem layout offsets (bytes)
#define SM_CAND   0
#define SM_H1T    (CAP * 8)                    // 8192
#define SM_H2T    (SM_H1T + 64 * 68 * 4)       // +17408
#define SM_W2     (SM_H2T + 64 * 68 * 4)       // +17408
#define SM_W3     (SM_W2 + 64 * 64 * 4)        // +16384
#define SM_W1P    (SM_W3 + 64 * 128 * 4)       // +32768
#define SM_B1     (SM_W1P + 192 * 4)
#define SM_B2     (SM_B1 + 64 * 4)
#define SM_B3     (SM_B2 + 64 * 4)
#define SM_MAX    (SM_B3 + 128 * 4)
#define SM_CNT    (SM_MAX + 128 * 4)
#define SMEM2     (SM_CNT + 64)

extern __shared__ char smem_raw[];

__global__ void __launch_bounds__(256, 2) sa_kernel(
    const float* __restrict__ W1, const float* __restrict__ b1,
    const float* __restrict__ W2, const float* __restrict__ b2,
    const float* __restrict__ W3, const float* __restrict__ b3,
    float* __restrict__ out, int out_size) {

    unsigned long long* cand = (unsigned long long*)(smem_raw + SM_CAND);
    float* h1T  = (float*)(smem_raw + SM_H1T);
    float* h2T  = (float*)(smem_raw + SM_H2T);
    float* W2s  = (float*)(smem_raw + SM_W2);
    float* W3s  = (float*)(smem_raw + SM_W3);
    float* W1ps = (float*)(smem_raw + SM_W1P);
    float* b1s  = (float*)(smem_raw + SM_B1);
    float* b2s  = (float*)(smem_raw + SM_B2);
    float* b3s  = (float*)(smem_raw + SM_B3);
    int*   smaxI = (int*)(smem_raw + SM_MAX);
    int*   scnt  = (int*)(smem_raw + SM_CNT);

    const int tid = threadIdx.x;
    const int row = blockIdx.x;              // global output row = b*MS + m
    const int b   = row >> 11;               // /MS
    const int g0  = b * NPB;

    // load weights / init
    for (int i = tid; i < 4096; i += 256) W2s[i] = W2[i];
    for (int i = tid; i < 8192; i += 256) W3s[i] = W3[i];
    if (tid < 192) W1ps[tid] = W1[64 * 64 + tid];
    if (tid < 64)  { b1s[tid] = b1[tid]; b2s[tid] = b2[tid]; }
    if (tid < 128) { b3s[tid] = b3[tid]; smaxI[tid] = 0; }
    if (tid == 0)  *scnt = 0;
    for (int i = tid; i < CAP; i += 256) cand[i] = 0xffffffffffffffffull;
    __syncthreads();

    int sl = g_samp[row];
    const float cx = g_px[g0 + sl], cy = g_py[g0 + sl], cz = g_pz[g0 + sl];
    const float R2 = (float)(0.2 * 0.2);

    // radius scan, packed pairs, coalesced SoA loads (exact fp32 semantics)
    {
        const unsigned long long* px2 = (const unsigned long long*)(g_px + g0);
        const unsigned long long* py2 = (const unsigned long long*)(g_py + g0);
        const unsigned long long* pz2 = (const unsigned long long*)(g_pz + g0);
        const unsigned long long ONE2 = pk2(1.0f, 1.0f);
        const unsigned long long ncx2 = pk2(-cx, -cx);
        const unsigned long long ncy2 = pk2(-cy, -cy);
        const unsigned long long ncz2 = pk2(-cz, -cz);
        for (int q = tid; q < NPB / 2; q += 256) {
            unsigned long long dx2 = fma2(px2[q], ONE2, ncx2);
            unsigned long long dy2 = fma2(py2[q], ONE2, ncy2);
            unsigned long long dz2 = fma2(pz2[q], ONE2, ncz2);
            unsigned long long d22 = add2(add2(mul2(dx2, dx2), mul2(dy2, dy2)), mul2(dz2, dz2));
            float d0, d1;
            upk2(d22, d0, d1);
            if (d0 <= R2) {
                int s = atomicAdd(scnt, 1);
                if (s < CAP)
                    cand[s] = ((unsigned long long)__float_as_uint(d0) << 32) | (unsigned)(2 * q);
            }
            if (d1 <= R2) {
                int s = atomicAdd(scnt, 1);
                if (s < CAP)
                    cand[s] = ((unsigned long long)__float_as_uint(d1) << 32) | (unsigned)(2 * q + 1);
            }
        }
    }
    __syncthreads();
    int n = *scnt; if (n > CAP) n = CAP;

    // bitonic sort only when needed, over next-pow2(n) region
    // (u64 keys: d2 bits major, index minor -> stable like lax.top_k; set of K
    //  smallest is all we need — maxpool is order-invariant)
    if (n > KNB) {
        int np2 = 128;
        while (np2 < n) np2 <<= 1;
        for (int k = 2; k <= np2; k <<= 1) {
            for (int j = k >> 1; j > 0; j >>= 1) {
                __syncthreads();
                for (int i = tid; i < np2; i += 256) {
                    int ixj = i ^ j;
                    if (ixj > i) {
                        unsigned long long a = cand[i], c2 = cand[ixj];
                        bool asc = ((i & k) == 0);
                        if ((a > c2) == asc) { cand[i] = c2; cand[ixj] = a; }
                    }
                }
            }
        }
    }
    __syncthreads();
    int nv = n < KNB ? n : KNB;

    // h1 = relu(X'[j] + relpos @ W1p + b1), stored transposed [c][n] with stride 68
    for (int p = tid; p < 64 * 64; p += 256) {
        int nn = p >> 6, c = p & 63;
        float v = 0.f;
        if (nn < nv) {
            int j = (int)(unsigned)(cand[nn] & 0xffffffffull);
            float rx = g_px[g0 + j] - cx;
            float ry = g_py[g0 + j] - cy;
            float rz = g_pz[g0 + j] - cz;
            v = g_xw1[(size_t)(g0 + j) * 64 + c];
            v = fmaf(rx, W1ps[c], v);
            v = fmaf(ry, W1ps[64 + c], v);
            v = fmaf(rz, W1ps[128 + c], v);
            v = fmaxf(v + b1s[c], 0.f);
        }
        h1T[c * 68 + nn] = v;
    }
    __syncthreads();

    // layer 2: h2 = relu(h1 @ W2 + b2); 4x4 register tiles
    {
        int tn = tid >> 4, tc = tid & 15;
        float acc[4][4];
        #pragma unroll
        for (int i = 0; i < 4; i++)
            #pragma unroll
            for (int j = 0; j < 4; j++) acc[i][j] = b2s[tc * 4 + j];
        #pragma unroll 8
        for (int k = 0; k < 64; k++) {
            float4 a = *(const float4*)(h1T + k * 68 + tn * 4);
            float4 w = *(const float4*)(W2s + k * 64 + tc * 4);
            const float av[4] = {a.x, a.y, a.z, a.w};
            const float wv[4] = {w.x, w.y, w.z, w.w};
            #pragma unroll
            for (int i = 0; i < 4; i++)
                #pragma unroll
                for (int j = 0; j < 4; j++) acc[i][j] = fmaf(av[i], wv[j], acc[i][j]);
        }
        #pragma unroll
        for (int i = 0; i < 4; i++)
            #pragma unroll
            for (int j = 0; j < 4; j++)
                h2T[(tc * 4 + j) * 68 + tn * 4 + i] = fmaxf(acc[i][j], 0.f);
    }
    __syncthreads();

    // layer 3: h3 = relu(h2 @ W3 + b3), fused maxpool over valid rows
    {
        int tn = tid >> 4, tc = tid & 15;
        float acc[4][8];
        #pragma unroll
        for (int i = 0; i < 4; i++)
            #pragma unroll
            for (int j = 0; j < 8; j++) acc[i][j] = b3s[tc * 8 + j];
        #pragma unroll 4
        for (int k = 0; k < 64; k++) {
            float4 a  = *(const float4*)(h2T + k * 68 + tn * 4);
            float4 w0 = *(const float4*)(W3s + k * 128 + tc * 8);
            float4 w1 = *(const float4*)(W3s + k * 128 + tc * 8 + 4);
            const float av[4] = {a.x, a.y, a.z, a.w};
            const float wv[8] = {w0.x, w0.y, w0.z, w0.w, w1.x, w1.y, w1.z, w1.w};
            #pragma unroll
            for (int i = 0; i < 4; i++)
                #pragma unroll
                for (int j = 0; j < 8; j++) acc[i][j] = fmaf(av[i], wv[j], acc[i][j]);
        }
        if (tn * 4 < nv) {  // at least one valid row in this tile
            int vrows = nv - tn * 4; if (vrows > 4) vrows = 4;
            #pragma unroll
            for (int j = 0; j < 8; j++) {
                float m = 0.f;
                for (int i = 0; i < vrows; i++) m = fmaxf(m, fmaxf(acc[i][j], 0.f));
                atomicMax(&smaxI[tc * 8 + j], __float_as_int(m));  // nonneg: int order == float order
            }
        }
    }
    __syncthreads();

    // outputs: [B*M,128] feat, then [B*M,3] pos, then [B*M] batch (as float)
    const int OUT1 = BATCH * MS * 128;
    const int OUT2 = OUT1 + BATCH * MS * 3;
    const int OUT3 = OUT2 + BATCH * MS;
    if (tid < 128) out[(size_t)row * 128 + tid] = __int_as_float(smaxI[tid]);
    if (out_size >= OUT2 && tid == 128) {
        float* po = out + OUT1 + (size_t)row * 3;
        po[0] = cx; po[1] = cy; po[2] = cz;
    }
    if (out_size >= OUT3 && tid == 129) out[OUT2 + row] = (float)b;
}

extern "C" void kernel_launch(void* const* d_in, const int* in_sizes, int n_in,
                              void* d_out, int out_size) {
    const float* x   = (const float*)d_in[0];
    const float* pos = (const float*)d_in[1];
    // d_in[2] = batch (implicit by layout)
    const float* W1 = (const float*)d_in[3];
    const float* b1 = (const float*)d_in[4];
    const float* W2 = (const float*)d_in[5];
    const float* b2 = (const float*)d_in[6];
    const float* W3 = (const float*)d_in[7];
    const float* b3 = (const float*)d_in[8];

    cudaFuncSetAttribute(sa_kernel, cudaFuncAttributeMaxDynamicSharedMemorySize, SMEM2);

    soa_kernel<<<NPTS / 256, 256>>>(pos);
    xw1_kernel<<<NPTS / 4, 256>>>(x, W1);
    fps_kernel<<<BATCH, 512>>>();
    sa_kernel<<<BATCH * MS, 256, SMEM2>>>(W1, b1, W2, b2, W3, b3,
                                          (float*)d_out, out_size);
}